// round 15
// baseline (speedup 1.0000x reference)
#include <cuda_runtime.h>
#include <cuda_bf16.h>

#define BH 32
#define SEQ 8192
#define D 64
#define BK 64
#define NB 128   /* q buckets (rows) */
#define NC 129   /* kv buckets + 1 (cols) */
#define PITCH 132

// ---------------------------------------------------------------------------
// Compile-time tables (double-accumulated, stored float)
// ---------------------------------------------------------------------------
struct Tables {
    float cw[SEQ];    // suffix harmonic within t's bucket
    float sH[NB];     // full-bucket harmonic
    float rq0[NB];    // 0.125 / (j*64+1)
};
constexpr Tables make_tables() {
    Tables t{};
    for (int j = 0; j < NB; j++) {
        double acc = 0.0;
        for (int s = BK - 1; s >= 0; s--) {
            acc += 1.0 / (double)(j * BK + s + 1);
            t.cw[j * BK + s] = (float)acc;
        }
        t.sH[j]  = (float)acc;
        t.rq0[j] = (float)(0.125 / (double)(j * BK + 1));
    }
    return t;
}
__device__ const Tables c_tab = make_tables();

// Scratch (device globals)
__device__ float4 g_Sq[BH*NB*16];      // per-bucket q sums
__device__ float4 g_Sk[BH*NB*16];      // per-bucket k sums
__device__ float4 g_Wk[BH*NB*16];      // within-bucket weighted k term
__device__ float4 g_sqT[BH*D*NB/4];    // sq transposed [b][e][j], pre-scaled
__device__ float  g_skTp[BH*D*PITCH];  // sk transposed PADDED [b][e][0..131]

// producer/consumer flags (zero-init; self-reset each replay)
__device__ unsigned g_cnt [BH];        // kA block completions per b (0..32)
__device__ unsigned g_scan[BH];        // scan-task completions per b (0..4)
__device__ unsigned g_gem [BH];        // GEMM passers per b (0..4) -> reset

__device__ __forceinline__ void spinGE(unsigned* p, unsigned v) {
    while (*(volatile unsigned*)p < v) __nanosleep(64);
}

// ---------------------------------------------------------------------------
// Kernel A: frozen R6 streaming core + per-b completion flag + early PDL.
// ---------------------------------------------------------------------------
__global__ void __launch_bounds__(256) kA(const float4* __restrict__ q,
                                          const float4* __restrict__ k) {
    __shared__ float4 sRq[4][4][16];
    __shared__ float4 sRk[4][4][16];
    __shared__ float4 sWp[4][4][16];

    int tid = threadIdx.x;
    // fire ASAP: dependent kT may launch once ALL kA CTAs have executed this
    // (i.e. when the last wave enters). kT's reads are gated by g_cnt flags.
    if (tid == 0) asm volatile("griddepcontrol.launch_dependents;");

    int bl  = tid >> 6;
    int r   = tid & 63;
    int sub = r >> 4;
    int l   = r & 15;
    int gb  = blockIdx.x * 4 + bl;
    int b   = blockIdx.x >> 5;
    int t0s = (gb & 127) * BK + sub * 16;

    const float4* qp = q + (size_t)gb * 1024 + sub * 256 + l;
    const float4* kp = k + (size_t)gb * 1024 + sub * 256 + l;
    const float*  cw = c_tab.cw + t0s;

    float4 rq = make_float4(0.f, 0.f, 0.f, 0.f);
    float4 rk = rq, wp = rq;

#pragma unroll 8
    for (int s = 0; s < 16; s++) {
        float4 qv = qp[s * 16];
        float4 kv = kp[s * 16];
        float  w  = cw[s];
        rq.x += qv.x; rq.y += qv.y; rq.z += qv.z; rq.w += qv.w;
        rk.x += kv.x; rk.y += kv.y; rk.z += kv.z; rk.w += kv.w;
        wp.x += kv.x * w; wp.y += kv.y * w; wp.z += kv.z * w; wp.w += kv.w * w;
    }

    sRq[bl][sub][l] = rq;
    sRk[bl][sub][l] = rk;
    sWp[bl][sub][l] = wp;
    __syncthreads();

    if (sub == 0) {
        float4 a, b4, c, d4;
        a = sRq[bl][0][l]; b4 = sRq[bl][1][l]; c = sRq[bl][2][l]; d4 = sRq[bl][3][l];
        g_Sq[gb * 16 + l] = make_float4(a.x+b4.x+c.x+d4.x, a.y+b4.y+c.y+d4.y,
                                        a.z+b4.z+c.z+d4.z, a.w+b4.w+c.w+d4.w);
        a = sRk[bl][0][l]; b4 = sRk[bl][1][l]; c = sRk[bl][2][l]; d4 = sRk[bl][3][l];
        g_Sk[gb * 16 + l] = make_float4(a.x+b4.x+c.x+d4.x, a.y+b4.y+c.y+d4.y,
                                        a.z+b4.z+c.z+d4.z, a.w+b4.w+c.w+d4.w);
        a = sWp[bl][0][l]; b4 = sWp[bl][1][l]; c = sWp[bl][2][l]; d4 = sWp[bl][3][l];
        g_Wk[gb * 16 + l] = make_float4(a.x+b4.x+c.x+d4.x, a.y+b4.y+c.y+d4.y,
                                        a.z+b4.z+c.z+d4.z, a.w+b4.w+c.w+d4.w);
    }
    __syncthreads();
    if (tid == 0) {
        __threadfence();                      // release this block's results
        atomicAdd(&g_cnt[b], 1u);
    }
}

// ---------------------------------------------------------------------------
// Kernel T: 128 CTAs x 512 thr, PDL-launched (overlaps kA's drain).
// CTA bid: scan task (b=bid>>2, which, e-half) gated on g_cnt[b]==32,
// then GEMM tile (same b, tile=bid&3) gated on g_scan[b]==4.
// No grid-wide barrier: fully pipelined across b.
// ---------------------------------------------------------------------------
__global__ void __launch_bounds__(512) kT(const float* __restrict__ qf,
                                          float* __restrict__ out) {
    __shared__ __align__(16) char smemraw[43200];

    int tid = threadIdx.x;
    int bid = blockIdx.x;
    int w   = tid >> 5, lane = tid & 31;

    int b     = bid >> 2;
    int which = (bid >> 1) & 1;            // 0 = q, 1 = k
    int eh    = (bid & 1) * 32;            // e-half base
    int base  = b * NB * D + eh;

    // ================= Phase 1: scan task ==================================
    {
        float* sA = (float*)smemraw;       // [32][PITCH]
        float* sB = sA + 32 * PITCH;

        if (!which) {
            // independent prologue: q bucket-firsts (reads only the input q)
            const float* qb = qf + (size_t)b * SEQ * D + eh;
            for (int idx = tid; idx < NB * 32; idx += 512) {
                int j = idx >> 5, el = idx & 31;
                sB[el * PITCH + j] = qb[(size_t)j * (BK * D) + el];
            }
        }

        if (tid == 0) spinGE(&g_cnt[b], 32u);
        __syncthreads();
        __threadfence();                   // acquire kA's writes for b

        if (!which) {
            const float* gS = (const float*)g_Sq + base;
            for (int idx = tid; idx < NB * 32; idx += 512) {
                int j = idx >> 5, el = idx & 31;
                sA[el * PITCH + j] = gS[j * 64 + el];
            }
        } else {
            const float* gS = (const float*)g_Sk + base;
            const float* gX = (const float*)g_Wk + base;
            for (int idx = tid; idx < NB * 32; idx += 512) {
                int j = idx >> 5, el = idx & 31;
                sA[el * PITCH + j] = gS[j * 64 + el];
                sB[el * PITCH + j] = gX[j * 64 + el];
            }
        }
        __syncthreads();

#pragma unroll
        for (int c = 0; c < 2; c++) {
            int el = w * 2 + c;
            int e  = eh + el;
            float4 v = *(const float4*)&sA[el * PITCH + lane * 4];
            float s01 = v.x + v.y, s012 = s01 + v.z, lsum = s012 + v.w;
            float run = lsum;
#pragma unroll
            for (int o = 1; o < 32; o <<= 1) {
                float tshf = __shfl_up_sync(0xffffffffu, run, o);
                if (lane >= o) run += tshf;
            }
            float excl = run - lsum;
            float p0 = excl, p1 = excl + v.x, p2 = excl + s01, p3 = excl + s012;
            int j0 = lane * 4;
            float4 xb = *(const float4*)&sB[el * PITCH + j0];
            if (!which) {
                float4 o4;
                o4.x = (p0 + xb.x) * c_tab.rq0[j0];
                o4.y = (p1 + xb.y) * c_tab.rq0[j0 + 1];
                o4.z = (p2 + xb.z) * c_tab.rq0[j0 + 2];
                o4.w = (p3 + xb.w) * c_tab.rq0[j0 + 3];
                g_sqT[(size_t)(b * 64 + e) * 32 + lane] = o4;
            } else {
                float* dst = g_skTp + (size_t)(b * 64 + e) * PITCH;
                if (lane == 0) { dst[0] = 0.f; dst[129] = 0.f; dst[130] = 0.f; dst[131] = 0.f; }
                dst[j0 + 1] = p0 * c_tab.sH[j0]     + xb.x;
                dst[j0 + 2] = p1 * c_tab.sH[j0 + 1] + xb.y;
                dst[j0 + 3] = p2 * c_tab.sH[j0 + 2] + xb.z;
                dst[j0 + 4] = p3 * c_tab.sH[j0 + 3] + xb.w;
            }
        }
        __syncthreads();
        if (tid == 0) {
            __threadfence();               // release scan outputs
            atomicAdd(&g_scan[b], 1u);
        }
    }

    // ================= Phase 2: GEMM + softmax tile ========================
    {
        float* skT = (float*)smemraw;      // [64][PITCH]  33.8 KB
        float* sqs = skT + D * PITCH;      // [32][65]

        int i0 = (bid & 3) * 32;

        if (tid == 0) {
            spinGE(&g_scan[b], 4u);
            if (atomicAdd(&g_gem[b], 1u) == 3u) {
                // all 4 consumers of b passed their spins: reset for replay
                g_cnt[b] = 0; g_scan[b] = 0; g_gem[b] = 0;
            }
        }
        __syncthreads();
        __threadfence();                   // acquire all 4 scans' outputs

        {
            const float4* src = (const float4*)(g_skTp + (size_t)b * D * PITCH);
            float4* dst = (float4*)skT;
            for (int idx = tid; idx < D * PITCH / 4; idx += 512)
                dst[idx] = src[idx];
        }
        {
            const float* srcq = (const float*)g_sqT;
            for (int idx = tid; idx < 32 * D; idx += 512) {
                int e = idx >> 5, jl = idx & 31;
                sqs[jl * 65 + e] = srcq[(size_t)(b * 64 + e) * NB + i0 + jl];
            }
        }
        __syncthreads();

        int rl0 = w * 2, rl1 = rl0 + 1;    // 16 warps x 2 rows = 32 rows
        float acc[2][5] = {{0,0,0,0,0},{0,0,0,0,0}};
#pragma unroll 8
        for (int e = 0; e < D; e++) {
            float a0 = sqs[rl0 * 65 + e];
            float a1 = sqs[rl1 * 65 + e];
            const float* row = skT + e * PITCH;
            float b0 = row[lane];
            float b1 = row[lane + 32];
            float b2 = row[lane + 64];
            float b3 = row[lane + 96];
            float b4 = row[128];
            acc[0][0] += a0 * b0; acc[1][0] += a1 * b0;
            acc[0][1] += a0 * b1; acc[1][1] += a1 * b1;
            acc[0][2] += a0 * b2; acc[1][2] += a1 * b2;
            acc[0][3] += a0 * b3; acc[1][3] += a1 * b3;
            acc[0][4] += a0 * b4; acc[1][4] += a1 * b4;
        }

#pragma unroll
        for (int rr = 0; rr < 2; rr++) {
            int i = i0 + rl0 + rr;
            float* v = acc[rr];

            float m = -3.402823466e+38f;
#pragma unroll
            for (int c = 0; c < 5; c++) {
                int jj = lane + 32 * c;
                if (jj <= i) m = fmaxf(m, v[c]);
            }
#pragma unroll
            for (int o = 16; o; o >>= 1)
                m = fmaxf(m, __shfl_xor_sync(0xffffffffu, m, o));

            float s = 0.0f;
#pragma unroll
            for (int c = 0; c < 5; c++) {
                int jj = lane + 32 * c;
                float ex = (jj <= i) ? __expf(v[c] - m) : 0.0f;
                v[c] = ex;
                s += ex;
            }
#pragma unroll
            for (int o = 16; o; o >>= 1)
                s += __shfl_xor_sync(0xffffffffu, s, o);
            float inv = __fdividef(1.0f, s);

            float* orow = out + ((size_t)(b * NB + i)) * NC;
#pragma unroll
            for (int c = 0; c < 5; c++) {
                int jj = lane + 32 * c;
                if (jj < NC) orow[jj] = (jj < i) ? v[c] * inv : 0.0f;
            }
        }
    }
}

// ---------------------------------------------------------------------------
extern "C" void kernel_launch(void* const* d_in, const int* in_sizes, int n_in,
                              void* d_out, int out_size) {
    const float4* q4 = (const float4*)d_in[0];
    const float4* k4 = (const float4*)d_in[1];
    const float*  qf = (const float*)d_in[0];
    float* out = (float*)d_out;

    kA<<<BH * NB / 4, 256>>>(q4, k4);

    // PDL: kT may begin while kA drains; all cross-kernel reads are gated by
    // per-b atomic flags (release/acquire), not griddepcontrol.wait.
    cudaLaunchConfig_t cfg = {};
    cfg.gridDim  = dim3(BH * 4, 1, 1);
    cfg.blockDim = dim3(512, 1, 1);
    cudaLaunchAttribute attrs[1];
    attrs[0].id = cudaLaunchAttributeProgrammaticStreamSerialization;
    attrs[0].val.programmaticStreamSerializationAllowed = 1;
    cfg.attrs = attrs;
    cfg.numAttrs = 1;
    cudaLaunchKernelEx(&cfg, kT, qf, out);
}

// round 16
// speedup vs baseline: 1.3024x; 1.3024x over previous
#include <cuda_runtime.h>
#include <cuda_bf16.h>

#define BH 32
#define SEQ 8192
#define D 64
#define BK 64
#define NB 128   /* q buckets (rows) */
#define NC 129   /* kv buckets + 1 (cols) */
#define PITCH 132
#define NCTA 148

// ---------------------------------------------------------------------------
// Compile-time tables (double-accumulated, stored float)
// ---------------------------------------------------------------------------
struct Tables {
    float cw[SEQ];    // suffix harmonic within t's bucket
    float sH[NB];     // full-bucket harmonic
    float rq0[NB];    // 0.125 / (j*64+1)
};
constexpr Tables make_tables() {
    Tables t{};
    for (int j = 0; j < NB; j++) {
        double acc = 0.0;
        for (int s = BK - 1; s >= 0; s--) {
            acc += 1.0 / (double)(j * BK + s + 1);
            t.cw[j * BK + s] = (float)acc;
        }
        t.sH[j]  = (float)acc;
        t.rq0[j] = (float)(0.125 / (double)(j * BK + 1));
    }
    return t;
}
__device__ const Tables c_tab = make_tables();

// Scratch (device globals)
__device__ float4 g_Sq[BH*NB*16];      // per-bucket q sums
__device__ float4 g_Sk[BH*NB*16];      // per-bucket k sums
__device__ float4 g_Wk[BH*NB*16];      // within-bucket weighted k term
__device__ float4 g_sqT[BH*D*NB/4];    // sq transposed [b][e][j], pre-scaled
__device__ float  g_skTp[BH*D*PITCH];  // sk transposed PADDED [b][e][0..131]

// grid barrier state (self-resetting; persists across graph replays)
__device__ unsigned g_barCnt = 0;
__device__ volatile unsigned g_barGen = 0;

__device__ __forceinline__ void gridBarrier() {
    __syncthreads();
    if (threadIdx.x == 0) {
        __threadfence();
        unsigned gen = g_barGen;
        if (atomicAdd(&g_barCnt, 1u) == NCTA - 1u) {
            g_barCnt = 0;
            __threadfence();
            g_barGen = gen + 1;
        } else {
            while (g_barGen == gen) { }
        }
        __threadfence();
    }
    __syncthreads();
}

// ---------------------------------------------------------------------------
// Kernel A (frozen R6 core; loads via __ldcs = streaming/evict-first).
// 1024 blocks x 256 threads.
// ---------------------------------------------------------------------------
__global__ void __launch_bounds__(256) kA(const float4* __restrict__ q,
                                          const float4* __restrict__ k) {
    __shared__ float4 sRq[4][4][16];
    __shared__ float4 sRk[4][4][16];
    __shared__ float4 sWp[4][4][16];

    int tid = threadIdx.x;
    int bl  = tid >> 6;
    int r   = tid & 63;
    int sub = r >> 4;
    int l   = r & 15;
    int gb  = blockIdx.x * 4 + bl;
    int t0s = (gb & 127) * BK + sub * 16;

    const float4* qp = q + (size_t)gb * 1024 + sub * 256 + l;
    const float4* kp = k + (size_t)gb * 1024 + sub * 256 + l;
    const float*  cw = c_tab.cw + t0s;

    float4 rq = make_float4(0.f, 0.f, 0.f, 0.f);
    float4 rk = rq, wp = rq;

#pragma unroll 8
    for (int s = 0; s < 16; s++) {
        float4 qv = __ldcs(qp + s * 16);
        float4 kv = __ldcs(kp + s * 16);
        float  w  = cw[s];
        rq.x += qv.x; rq.y += qv.y; rq.z += qv.z; rq.w += qv.w;
        rk.x += kv.x; rk.y += kv.y; rk.z += kv.z; rk.w += kv.w;
        wp.x += kv.x * w; wp.y += kv.y * w; wp.z += kv.z * w; wp.w += kv.w * w;
    }

    sRq[bl][sub][l] = rq;
    sRk[bl][sub][l] = rk;
    sWp[bl][sub][l] = wp;
    __syncthreads();

    if (sub == 0) {
        float4 a, b4, c, d4;
        a = sRq[bl][0][l]; b4 = sRq[bl][1][l]; c = sRq[bl][2][l]; d4 = sRq[bl][3][l];
        g_Sq[gb * 16 + l] = make_float4(a.x+b4.x+c.x+d4.x, a.y+b4.y+c.y+d4.y,
                                        a.z+b4.z+c.z+d4.z, a.w+b4.w+c.w+d4.w);
        a = sRk[bl][0][l]; b4 = sRk[bl][1][l]; c = sRk[bl][2][l]; d4 = sRk[bl][3][l];
        g_Sk[gb * 16 + l] = make_float4(a.x+b4.x+c.x+d4.x, a.y+b4.y+c.y+d4.y,
                                        a.z+b4.z+c.z+d4.z, a.w+b4.w+c.w+d4.w);
        a = sWp[bl][0][l]; b4 = sWp[bl][1][l]; c = sWp[bl][2][l]; d4 = sWp[bl][3][l];
        g_Wk[gb * 16 + l] = make_float4(a.x+b4.x+c.x+d4.x, a.y+b4.y+c.y+d4.y,
                                        a.z+b4.z+c.z+d4.z, a.w+b4.w+c.w+d4.w);
    }
}

// ---------------------------------------------------------------------------
// Kernel T (exact R11): persistent tail. Phase 1 = scans (128 tasks:
// b x q|k x e-half, one wave) -> grid barrier -> Phase 2 = GEMM+softmax
// (128 32-row tiles, one wave). 148 CTAs x 512 threads.
// ---------------------------------------------------------------------------
__global__ void __launch_bounds__(512) kT(const float* __restrict__ qf,
                                          float* __restrict__ out) {
    __shared__ __align__(16) char smemraw[43200];

    int tid = threadIdx.x;
    int w   = tid >> 5, lane = tid & 31;

    // ================= Phase 1: scans (128 tasks, one wave) ================
    if (blockIdx.x < BH * 4) {
        float* sA = (float*)smemraw;       // [32][PITCH]
        float* sB = sA + 32 * PITCH;

        int tk    = blockIdx.x;
        int b     = tk >> 2;
        int which = (tk >> 1) & 1;         // 0 = q, 1 = k
        int eh    = (tk & 1) * 32;         // e-half base
        int base  = b * NB * D + eh;

        const float* gS = (const float*)(which ? g_Sk : g_Sq) + base;
        if (which) {
            const float* gX = (const float*)g_Wk + base;
            for (int idx = tid; idx < NB * 32; idx += 512) {
                int j = idx >> 5, el = idx & 31;
                sA[el * PITCH + j] = gS[j * 64 + el];
                sB[el * PITCH + j] = gX[j * 64 + el];
            }
        } else {
            const float* qb = qf + (size_t)b * SEQ * D + eh;
            for (int idx = tid; idx < NB * 32; idx += 512) {
                int j = idx >> 5, el = idx & 31;
                sA[el * PITCH + j] = gS[j * 64 + el];
                sB[el * PITCH + j] = qb[(size_t)j * (BK * D) + el];
            }
        }
        __syncthreads();

#pragma unroll
        for (int c = 0; c < 2; c++) {
            int el = w * 2 + c;
            int e  = eh + el;
            float4 v = *(const float4*)&sA[el * PITCH + lane * 4];
            float s01 = v.x + v.y, s012 = s01 + v.z, lsum = s012 + v.w;
            float run = lsum;
#pragma unroll
            for (int o = 1; o < 32; o <<= 1) {
                float tshf = __shfl_up_sync(0xffffffffu, run, o);
                if (lane >= o) run += tshf;
            }
            float excl = run - lsum;
            float p0 = excl, p1 = excl + v.x, p2 = excl + s01, p3 = excl + s012;
            int j0 = lane * 4;
            float4 xb = *(const float4*)&sB[el * PITCH + j0];
            if (!which) {
                float4 o4;
                o4.x = (p0 + xb.x) * c_tab.rq0[j0];
                o4.y = (p1 + xb.y) * c_tab.rq0[j0 + 1];
                o4.z = (p2 + xb.z) * c_tab.rq0[j0 + 2];
                o4.w = (p3 + xb.w) * c_tab.rq0[j0 + 3];
                g_sqT[(size_t)(b * 64 + e) * 32 + lane] = o4;
            } else {
                float* dst = g_skTp + (size_t)(b * 64 + e) * PITCH;
                if (lane == 0) { dst[0] = 0.f; dst[129] = 0.f; dst[130] = 0.f; dst[131] = 0.f; }
                dst[j0 + 1] = p0 * c_tab.sH[j0]     + xb.x;
                dst[j0 + 2] = p1 * c_tab.sH[j0 + 1] + xb.y;
                dst[j0 + 3] = p2 * c_tab.sH[j0 + 2] + xb.z;
                dst[j0 + 4] = p3 * c_tab.sH[j0 + 3] + xb.w;
            }
        }
    }

    gridBarrier();

    // ================= Phase 2: GEMM + softmax (128 tiles, one wave) =======
    if (blockIdx.x < BH * 4) {
        float* skT = (float*)smemraw;      // [64][PITCH]
        float* sqs = skT + D * PITCH;      // [32][65]

        int t  = blockIdx.x;
        int b  = t >> 2;
        int i0 = (t & 3) * 32;

        {
            const float4* src = (const float4*)(g_skTp + (size_t)b * D * PITCH);
            float4* dst = (float4*)skT;
            for (int idx = tid; idx < D * PITCH / 4; idx += 512)
                dst[idx] = src[idx];
        }
        {
            const float* srcq = (const float*)g_sqT;
            for (int idx = tid; idx < 32 * D; idx += 512) {
                int e = idx >> 5, jl = idx & 31;
                sqs[jl * 65 + e] = srcq[(size_t)(b * 64 + e) * NB + i0 + jl];
            }
        }
        __syncthreads();

        int rl0 = w * 2, rl1 = rl0 + 1;
        float acc[2][5] = {{0,0,0,0,0},{0,0,0,0,0}};
#pragma unroll 8
        for (int e = 0; e < D; e++) {
            float a0 = sqs[rl0 * 65 + e];
            float a1 = sqs[rl1 * 65 + e];
            const float* row = skT + e * PITCH;
            float b0 = row[lane];
            float b1 = row[lane + 32];
            float b2 = row[lane + 64];
            float b3 = row[lane + 96];
            float b4 = row[128];
            acc[0][0] += a0 * b0; acc[1][0] += a1 * b0;
            acc[0][1] += a0 * b1; acc[1][1] += a1 * b1;
            acc[0][2] += a0 * b2; acc[1][2] += a1 * b2;
            acc[0][3] += a0 * b3; acc[1][3] += a1 * b3;
            acc[0][4] += a0 * b4; acc[1][4] += a1 * b4;
        }

#pragma unroll
        for (int rr = 0; rr < 2; rr++) {
            int i = i0 + rl0 + rr;
            float* v = acc[rr];

            float m = -3.402823466e+38f;
#pragma unroll
            for (int c = 0; c < 5; c++) {
                int jj = lane + 32 * c;
                if (jj <= i) m = fmaxf(m, v[c]);
            }
#pragma unroll
            for (int o = 16; o; o >>= 1)
                m = fmaxf(m, __shfl_xor_sync(0xffffffffu, m, o));

            float s = 0.0f;
#pragma unroll
            for (int c = 0; c < 5; c++) {
                int jj = lane + 32 * c;
                float ex = (jj <= i) ? __expf(v[c] - m) : 0.0f;
                v[c] = ex;
                s += ex;
            }
#pragma unroll
            for (int o = 16; o; o >>= 1)
                s += __shfl_xor_sync(0xffffffffu, s, o);
            float inv = __fdividef(1.0f, s);

            float* orow = out + ((size_t)(b * NB + i)) * NC;
#pragma unroll
            for (int c = 0; c < 5; c++) {
                int jj = lane + 32 * c;
                if (jj < NC) orow[jj] = (jj < i) ? v[c] * inv : 0.0f;
            }
        }
    }
}

// ---------------------------------------------------------------------------
extern "C" void kernel_launch(void* const* d_in, const int* in_sizes, int n_in,
                              void* d_out, int out_size) {
    const float4* q4 = (const float4*)d_in[0];
    const float4* k4 = (const float4*)d_in[1];
    const float*  qf = (const float*)d_in[0];
    float* out = (float*)d_out;

    kA<<<BH * NB / 4, 256>>>(q4, k4);
    kT<<<NCTA, 512>>>(qf, out);
}

// round 17
// speedup vs baseline: 1.3552x; 1.0406x over previous
#include <cuda_runtime.h>
#include <cuda_bf16.h>

#define BH 32
#define SEQ 8192
#define D 64
#define BK 64
#define NB 128   /* q buckets (rows) */
#define NC 129   /* kv buckets + 1 (cols) */
#define PITCH 132
#define NCTA 128

// ---------------------------------------------------------------------------
// Compile-time tables (double-accumulated, stored float)
// ---------------------------------------------------------------------------
struct Tables {
    float cw[SEQ];    // suffix harmonic within t's bucket
    float sH[NB];     // full-bucket harmonic
    float rq0[NB];    // 0.125 / (j*64+1)
};
constexpr Tables make_tables() {
    Tables t{};
    for (int j = 0; j < NB; j++) {
        double acc = 0.0;
        for (int s = BK - 1; s >= 0; s--) {
            acc += 1.0 / (double)(j * BK + s + 1);
            t.cw[j * BK + s] = (float)acc;
        }
        t.sH[j]  = (float)acc;
        t.rq0[j] = (float)(0.125 / (double)(j * BK + 1));
    }
    return t;
}
__device__ const Tables c_tab = make_tables();

// Scratch (device globals)
__device__ float4 g_Sq[BH*NB*16];      // per-bucket q sums
__device__ float4 g_Sk[BH*NB*16];      // per-bucket k sums
__device__ float4 g_Wk[BH*NB*16];      // within-bucket weighted k term
__device__ float4 g_sqT[BH*D*NB/4];    // sq transposed [b][e][j], pre-scaled
__device__ float  g_skTp[BH*D*PITCH];  // sk transposed PADDED [b][e][0..131]

// grid barrier state (self-resetting; persists across graph replays)
__device__ unsigned g_barCnt = 0;
__device__ volatile unsigned g_barGen = 0;

__device__ __forceinline__ void gridBarrier() {
    __syncthreads();
    if (threadIdx.x == 0) {
        __threadfence();
        unsigned gen = g_barGen;
        if (atomicAdd(&g_barCnt, 1u) == NCTA - 1u) {
            g_barCnt = 0;
            __threadfence();
            g_barGen = gen + 1;
        } else {
            while (g_barGen == gen) { }
        }
        __threadfence();
    }
    __syncthreads();
}

// ---------------------------------------------------------------------------
// Kernel A (frozen R16: R6 core + __ldcs streaming loads).
// 1024 blocks x 256 threads.
// ---------------------------------------------------------------------------
__global__ void __launch_bounds__(256) kA(const float4* __restrict__ q,
                                          const float4* __restrict__ k) {
    __shared__ float4 sRq[4][4][16];
    __shared__ float4 sRk[4][4][16];
    __shared__ float4 sWp[4][4][16];

    int tid = threadIdx.x;
    int bl  = tid >> 6;
    int r   = tid & 63;
    int sub = r >> 4;
    int l   = r & 15;
    int gb  = blockIdx.x * 4 + bl;
    int t0s = (gb & 127) * BK + sub * 16;

    const float4* qp = q + (size_t)gb * 1024 + sub * 256 + l;
    const float4* kp = k + (size_t)gb * 1024 + sub * 256 + l;
    const float*  cw = c_tab.cw + t0s;

    float4 rq = make_float4(0.f, 0.f, 0.f, 0.f);
    float4 rk = rq, wp = rq;

#pragma unroll 8
    for (int s = 0; s < 16; s++) {
        float4 qv = __ldcs(qp + s * 16);
        float4 kv = __ldcs(kp + s * 16);
        float  w  = cw[s];
        rq.x += qv.x; rq.y += qv.y; rq.z += qv.z; rq.w += qv.w;
        rk.x += kv.x; rk.y += kv.y; rk.z += kv.z; rk.w += kv.w;
        wp.x += kv.x * w; wp.y += kv.y * w; wp.z += kv.z * w; wp.w += kv.w * w;
    }

    sRq[bl][sub][l] = rq;
    sRk[bl][sub][l] = rk;
    sWp[bl][sub][l] = wp;
    __syncthreads();

    if (sub == 0) {
        float4 a, b4, c, d4;
        a = sRq[bl][0][l]; b4 = sRq[bl][1][l]; c = sRq[bl][2][l]; d4 = sRq[bl][3][l];
        g_Sq[gb * 16 + l] = make_float4(a.x+b4.x+c.x+d4.x, a.y+b4.y+c.y+d4.y,
                                        a.z+b4.z+c.z+d4.z, a.w+b4.w+c.w+d4.w);
        a = sRk[bl][0][l]; b4 = sRk[bl][1][l]; c = sRk[bl][2][l]; d4 = sRk[bl][3][l];
        g_Sk[gb * 16 + l] = make_float4(a.x+b4.x+c.x+d4.x, a.y+b4.y+c.y+d4.y,
                                        a.z+b4.z+c.z+d4.z, a.w+b4.w+c.w+d4.w);
        a = sWp[bl][0][l]; b4 = sWp[bl][1][l]; c = sWp[bl][2][l]; d4 = sWp[bl][3][l];
        g_Wk[gb * 16 + l] = make_float4(a.x+b4.x+c.x+d4.x, a.y+b4.y+c.y+d4.y,
                                        a.z+b4.z+c.z+d4.z, a.w+b4.w+c.w+d4.w);
    }
}

// ---------------------------------------------------------------------------
// Kernel T: persistent tail, 128 CTAs x 512 threads (all working).
// Phase 1 = scans (128 tasks). Phase 2 = GEMM+softmax, 128 live columns,
// float4 skT loads (col 128 is provably always zero in the output).
// ---------------------------------------------------------------------------
__global__ void __launch_bounds__(512) kT(const float* __restrict__ qf,
                                          float* __restrict__ out) {
    __shared__ __align__(16) char smemraw[43200];

    int tid = threadIdx.x;
    int w   = tid >> 5, lane = tid & 31;

    // ================= Phase 1: scans (128 tasks, one wave) ================
    {
        float* sA = (float*)smemraw;       // [32][PITCH]
        float* sB = sA + 32 * PITCH;

        int tk    = blockIdx.x;
        int b     = tk >> 2;
        int which = (tk >> 1) & 1;         // 0 = q, 1 = k
        int eh    = (tk & 1) * 32;         // e-half base
        int base  = b * NB * D + eh;

        const float* gS = (const float*)(which ? g_Sk : g_Sq) + base;
        if (which) {
            const float* gX = (const float*)g_Wk + base;
            for (int idx = tid; idx < NB * 32; idx += 512) {
                int j = idx >> 5, el = idx & 31;
                sA[el * PITCH + j] = gS[j * 64 + el];
                sB[el * PITCH + j] = gX[j * 64 + el];
            }
        } else {
            const float* qb = qf + (size_t)b * SEQ * D + eh;
            for (int idx = tid; idx < NB * 32; idx += 512) {
                int j = idx >> 5, el = idx & 31;
                sA[el * PITCH + j] = gS[j * 64 + el];
                sB[el * PITCH + j] = qb[(size_t)j * (BK * D) + el];
            }
        }
        __syncthreads();

#pragma unroll
        for (int c = 0; c < 2; c++) {
            int el = w * 2 + c;
            int e  = eh + el;
            float4 v = *(const float4*)&sA[el * PITCH + lane * 4];
            float s01 = v.x + v.y, s012 = s01 + v.z, lsum = s012 + v.w;
            float run = lsum;
#pragma unroll
            for (int o = 1; o < 32; o <<= 1) {
                float tshf = __shfl_up_sync(0xffffffffu, run, o);
                if (lane >= o) run += tshf;
            }
            float excl = run - lsum;
            float p0 = excl, p1 = excl + v.x, p2 = excl + s01, p3 = excl + s012;
            int j0 = lane * 4;
            float4 xb = *(const float4*)&sB[el * PITCH + j0];
            if (!which) {
                float4 o4;
                o4.x = (p0 + xb.x) * c_tab.rq0[j0];
                o4.y = (p1 + xb.y) * c_tab.rq0[j0 + 1];
                o4.z = (p2 + xb.z) * c_tab.rq0[j0 + 2];
                o4.w = (p3 + xb.w) * c_tab.rq0[j0 + 3];
                g_sqT[(size_t)(b * 64 + e) * 32 + lane] = o4;
            } else {
                float* dst = g_skTp + (size_t)(b * 64 + e) * PITCH;
                if (lane == 0) { dst[0] = 0.f; dst[129] = 0.f; dst[130] = 0.f; dst[131] = 0.f; }
                dst[j0 + 1] = p0 * c_tab.sH[j0]     + xb.x;
                dst[j0 + 2] = p1 * c_tab.sH[j0 + 1] + xb.y;
                dst[j0 + 3] = p2 * c_tab.sH[j0 + 2] + xb.z;
                dst[j0 + 4] = p3 * c_tab.sH[j0 + 3] + xb.w;
            }
        }
    }

    gridBarrier();

    // ================= Phase 2: GEMM + softmax (128 tiles, one wave) =======
    // Output col 128 is always 0 (mask col>row kills it in softmax for all
    // rows i<128; col<row never holds for col 128) -> drop it from the GEMM.
    {
        float* skT = (float*)smemraw;      // [64][PITCH]
        float* sqs = skT + D * PITCH;      // [32][65]

        int t  = blockIdx.x;
        int b  = t >> 2;
        int i0 = (t & 3) * 32;

        {
            const float4* src = (const float4*)(g_skTp + (size_t)b * D * PITCH);
            float4* dst = (float4*)skT;
            for (int idx = tid; idx < D * PITCH / 4; idx += 512)
                dst[idx] = src[idx];
        }
        {
            const float* srcq = (const float*)g_sqT;
            for (int idx = tid; idx < 32 * D; idx += 512) {
                int e = idx >> 5, jl = idx & 31;
                sqs[jl * 65 + e] = srcq[(size_t)(b * 64 + e) * NB + i0 + jl];
            }
        }
        __syncthreads();

        int rl0 = w * 2, rl1 = rl0 + 1;    // 16 warps x 2 rows = 32 rows
        float4 acc0 = make_float4(0.f, 0.f, 0.f, 0.f);
        float4 acc1 = acc0;
#pragma unroll 8
        for (int e = 0; e < D; e++) {
            float a0 = sqs[rl0 * 65 + e];
            float a1 = sqs[rl1 * 65 + e];
            float4 bv = *(const float4*)&skT[e * PITCH + lane * 4];
            acc0.x += a0 * bv.x; acc1.x += a1 * bv.x;
            acc0.y += a0 * bv.y; acc1.y += a1 * bv.y;
            acc0.z += a0 * bv.z; acc1.z += a1 * bv.z;
            acc0.w += a0 * bv.w; acc1.w += a1 * bv.w;
        }

        float vr[2][4] = {{acc0.x, acc0.y, acc0.z, acc0.w},
                          {acc1.x, acc1.y, acc1.z, acc1.w}};
        int j0 = lane * 4;

#pragma unroll
        for (int rr = 0; rr < 2; rr++) {
            int i = i0 + rl0 + rr;
            float* v = vr[rr];

            float m = -3.402823466e+38f;
#pragma unroll
            for (int c = 0; c < 4; c++) {
                int jj = j0 + c;
                if (jj <= i) m = fmaxf(m, v[c]);
            }
#pragma unroll
            for (int o = 16; o; o >>= 1)
                m = fmaxf(m, __shfl_xor_sync(0xffffffffu, m, o));

            float s = 0.0f;
#pragma unroll
            for (int c = 0; c < 4; c++) {
                int jj = j0 + c;
                float ex = (jj <= i) ? __expf(v[c] - m) : 0.0f;
                v[c] = ex;
                s += ex;
            }
#pragma unroll
            for (int o = 16; o; o >>= 1)
                s += __shfl_xor_sync(0xffffffffu, s, o);
            float inv = __fdividef(1.0f, s);

            float* orow = out + ((size_t)(b * NB + i)) * NC;
#pragma unroll
            for (int c = 0; c < 4; c++) {
                int jj = j0 + c;
                orow[jj] = (jj < i) ? v[c] * inv : 0.0f;
            }
            if (lane == 0) orow[128] = 0.0f;
        }
    }
}

// ---------------------------------------------------------------------------
extern "C" void kernel_launch(void* const* d_in, const int* in_sizes, int n_in,
                              void* d_out, int out_size) {
    const float4* q4 = (const float4*)d_in[0];
    const float4* k4 = (const float4*)d_in[1];
    const float*  qf = (const float*)d_in[0];
    float* out = (float*)d_out;

    kA<<<BH * NB / 4, 256>>>(q4, k4);
    kT<<<NCTA, 512>>>(qf, out);
}